// round 3
// baseline (speedup 1.0000x reference)
#include <cuda_runtime.h>
#include <cuda_bf16.h>
#include <math.h>

// ---------------------------------------------------------------------------
// MambaSSMBlock: B=2, L=2048, D_MODEL=1024, D_INNER=2048, D_STATE=16,
// D_CONV=4, DT_RANK=64.  BL = 4096 rows.
//
// Pipeline:
//  1. xz   = x @ in_proj_w^T                      (4096 x 4096)
//  2. xc   = SiLU(causal depthwise conv(xin)+b)   (4096 x 2048)
//  3. xdbl = xc @ x_proj_w^T                      (4096 x 96)
//  4. delta= softplus(xdbl[:, :64] @ dt_w^T + b)  (4096 x 2048)
//  5. chunked selective scan -> y (fused D-skip + SiLU(z) gate)
//  6. mid  = y @ ssm_out_w^T                      (4096 x 1024)
//  7. out  = SiLU(mid @ final_w^T + b)            (4096 x 1024)
// ---------------------------------------------------------------------------

#define BB 2
#define LL 2048
#define DMODEL 1024
#define DINNER 2048
#define DSTATE 16
#define DTRANK 64
#define BL (BB * LL)
#define NCHUNK 16
#define CLEN (LL / NCHUNK)   // 128

// ------------------------- scratch (device globals) ------------------------
__device__ float g_xz[(size_t)BL * 2 * DINNER];     // 4096 x 4096
__device__ float g_xc[(size_t)BL * DINNER];         // 4096 x 2048
__device__ float g_xdbl[(size_t)BL * 96];           // 4096 x 96
__device__ float g_delta[(size_t)BL * DINNER];      // 4096 x 2048
__device__ float g_y[(size_t)BL * DINNER];          // 4096 x 2048
__device__ float g_mid[(size_t)BL * DMODEL];        // 4096 x 1024
__device__ float g_P[(size_t)BB * DINNER * NCHUNK * DSTATE];
__device__ float g_He[(size_t)BB * DINNER * NCHUNK * DSTATE];
__device__ float g_Hi[(size_t)BB * DINNER * NCHUNK * DSTATE];

// ------------------------------ helpers ------------------------------------
__device__ __forceinline__ float siluf(float x) {
    return x / (1.0f + __expf(-x));
}
__device__ __forceinline__ float softplusf(float x) {
    return (x > 20.0f) ? x : log1pf(__expf(x));
}

enum { EPI_NONE = 0, EPI_SOFTPLUS = 1, EPI_SILU = 2 };

// ------------------------------ generic GEMM --------------------------------
// C[M,N] = A[M,K] * B[N,K]^T  (+ bias + activation epilogue)
// A row-major lda, B row-major ldb (weights are (out_features, in_features)),
// C row-major ldc.  M must be a multiple of BM; N may be ragged.
template <int BM, int BN, int BK, int TM, int TN, int EPI>
__global__ void __launch_bounds__((BM / TM) * (BN / TN))
gemm_nt(const float* __restrict__ A, int lda,
        const float* __restrict__ B, int ldb,
        float* __restrict__ C, int ldc,
        int M, int N, int K,
        const float* __restrict__ bias)
{
    constexpr int NT = (BM / TM) * (BN / TN);
    __shared__ float As[BK][BM];
    __shared__ float Bs[BK][BN];

    const int tid = threadIdx.x;
    const int tx = tid % (BN / TN);
    const int ty = tid / (BN / TN);
    const int m0 = blockIdx.y * BM;
    const int n0 = blockIdx.x * BN;

    float acc[TM][TN];
#pragma unroll
    for (int i = 0; i < TM; i++)
#pragma unroll
        for (int j = 0; j < TN; j++) acc[i][j] = 0.0f;

    for (int k0 = 0; k0 < K; k0 += BK) {
        // cooperative load of A tile (stored transposed: As[k][m])
        for (int i = tid * 4; i < BM * BK; i += NT * 4) {
            int r = i / BK, c = i % BK;
            float4 v = *(const float4*)(A + (size_t)(m0 + r) * lda + k0 + c);
            As[c + 0][r] = v.x; As[c + 1][r] = v.y;
            As[c + 2][r] = v.z; As[c + 3][r] = v.w;
        }
        // cooperative load of B tile (Bs[k][n]) with N guard
        for (int i = tid * 4; i < BN * BK; i += NT * 4) {
            int r = i / BK, c = i % BK;
            int gn = n0 + r;
            float4 v = make_float4(0.f, 0.f, 0.f, 0.f);
            if (gn < N) v = *(const float4*)(B + (size_t)gn * ldb + k0 + c);
            Bs[c + 0][r] = v.x; Bs[c + 1][r] = v.y;
            Bs[c + 2][r] = v.z; Bs[c + 3][r] = v.w;
        }
        __syncthreads();

#pragma unroll
        for (int kk = 0; kk < BK; kk++) {
            float ar[TM], br[TN];
#pragma unroll
            for (int i = 0; i < TM; i++) ar[i] = As[kk][ty * TM + i];
#pragma unroll
            for (int j = 0; j < TN; j++) br[j] = Bs[kk][tx * TN + j];
#pragma unroll
            for (int i = 0; i < TM; i++)
#pragma unroll
                for (int j = 0; j < TN; j++)
                    acc[i][j] = fmaf(ar[i], br[j], acc[i][j]);
        }
        __syncthreads();
    }

#pragma unroll
    for (int i = 0; i < TM; i++) {
        int m = m0 + ty * TM + i;
#pragma unroll
        for (int j = 0; j < TN; j++) {
            int n = n0 + tx * TN + j;
            if (n < N) {
                float v = acc[i][j];
                if (EPI == EPI_SOFTPLUS) v = softplusf(v + bias[n]);
                else if (EPI == EPI_SILU) v = siluf(v + bias[n]);
                C[(size_t)m * ldc + n] = v;
            }
        }
    }
}

// ------------------------ conv1d (causal depthwise) + SiLU ------------------
// xin = g_xz[:, 0:DINNER].  Each thread handles 8 consecutive l for one d.
__global__ void __launch_bounds__(256)
conv_silu_kernel(const float* __restrict__ xz,
                 const float* __restrict__ conv_w,
                 const float* __restrict__ conv_b,
                 float* __restrict__ xc)
{
    const int d = blockIdx.x * 256 + threadIdx.x;     // 0..2047
    const int l0 = blockIdx.y * 8;                    // 0..2040
    const int b = blockIdx.z;

    const float w0 = conv_w[d * 4 + 0];
    const float w1 = conv_w[d * 4 + 1];
    const float w2 = conv_w[d * 4 + 2];
    const float w3 = conv_w[d * 4 + 3];
    const float cb = conv_b[d];

    float xv[11];
#pragma unroll
    for (int j = 0; j < 11; j++) {
        int l = l0 - 3 + j;
        xv[j] = (l >= 0) ? xz[((size_t)(b * LL + l)) * (2 * DINNER) + d] : 0.0f;
    }
#pragma unroll
    for (int i = 0; i < 8; i++) {
        float s = w0 * xv[i] + w1 * xv[i + 1] + w2 * xv[i + 2] + w3 * xv[i + 3] + cb;
        xc[((size_t)(b * LL + l0 + i)) * DINNER + d] = siluf(s);
    }
}

// ------------------------ selective scan: 3-phase chunked -------------------
// Phase A: per (b, d, chunk): local scan with h0=0; record per-state decay
// product P[n] = prod_t exp(delta_t * A[n]) and local end-state h_end[n].
__global__ void __launch_bounds__(256)
scan_phaseA(const float* __restrict__ delta,
            const float* __restrict__ xc,
            const float* __restrict__ xdbl,
            const float* __restrict__ A_log,
            float* __restrict__ Pout,
            float* __restrict__ Hend)
{
    const int d = blockIdx.x * 256 + threadIdx.x;
    const int c = blockIdx.y;
    const int b = blockIdx.z;

    float A2[DSTATE], h[DSTATE], P[DSTATE];
#pragma unroll
    for (int n = 0; n < DSTATE; n++) {
        A2[n] = -__expf(A_log[d * DSTATE + n]);
        h[n] = 0.0f;
        P[n] = 1.0f;
    }

    const size_t row0 = (size_t)(b * LL + c * CLEN);
    const float* drow = delta + row0 * DINNER + d;
    const float* urow = xc + row0 * DINNER + d;
    const float* bcrow = xdbl + row0 * 96 + 64;   // B_t at +64, C_t at +80

    for (int t = 0; t < CLEN; t++) {
        float dlt = drow[(size_t)t * DINNER];
        float du = dlt * urow[(size_t)t * DINNER];
        const float4* bc = (const float4*)(bcrow + (size_t)t * 96);
        float Bv[DSTATE];
        float4 q;
        q = bc[0]; Bv[0] = q.x; Bv[1] = q.y; Bv[2] = q.z; Bv[3] = q.w;
        q = bc[1]; Bv[4] = q.x; Bv[5] = q.y; Bv[6] = q.z; Bv[7] = q.w;
        q = bc[2]; Bv[8] = q.x; Bv[9] = q.y; Bv[10] = q.z; Bv[11] = q.w;
        q = bc[3]; Bv[12] = q.x; Bv[13] = q.y; Bv[14] = q.z; Bv[15] = q.w;
#pragma unroll
        for (int n = 0; n < DSTATE; n++) {
            float a = __expf(dlt * A2[n]);
            P[n] *= a;
            h[n] = fmaf(a, h[n], du * Bv[n]);
        }
    }
    const size_t o = (((size_t)(b * DINNER + d)) * NCHUNK + c) * DSTATE;
#pragma unroll
    for (int n = 0; n < DSTATE; n++) {
        Pout[o + n] = P[n];
        Hend[o + n] = h[n];
    }
}

// Phase B: serial combine over the 16 chunks; one thread per (b, d, n).
__global__ void __launch_bounds__(256)
scan_phaseB(const float* __restrict__ P,
            const float* __restrict__ He,
            float* __restrict__ Hi)
{
    const int idx = blockIdx.x * 256 + threadIdx.x;   // 0 .. B*DINNER*DSTATE-1
    const int n = idx % DSTATE;
    const int bd = idx / DSTATE;
    float h = 0.0f;
    for (int c = 0; c < NCHUNK; c++) {
        const size_t o = (((size_t)bd) * NCHUNK + c) * DSTATE + n;
        Hi[o] = h;
        h = P[o] * h + He[o];
    }
}

// Phase C: rerun each chunk from the corrected initial state; emit
// y = (sum_n h[n]*C[n] + u*D) * SiLU(z), fully fused.
__global__ void __launch_bounds__(256)
scan_phaseC(const float* __restrict__ delta,
            const float* __restrict__ xc,
            const float* __restrict__ xdbl,
            const float* __restrict__ A_log,
            const float* __restrict__ Dw,
            const float* __restrict__ xz,
            const float* __restrict__ Hi,
            float* __restrict__ y)
{
    const int d = blockIdx.x * 256 + threadIdx.x;
    const int c = blockIdx.y;
    const int b = blockIdx.z;

    float A2[DSTATE], h[DSTATE];
    const size_t ho = (((size_t)(b * DINNER + d)) * NCHUNK + c) * DSTATE;
#pragma unroll
    for (int n = 0; n < DSTATE; n++) {
        A2[n] = -__expf(A_log[d * DSTATE + n]);
        h[n] = Hi[ho + n];
    }
    const float Dd = Dw[d];

    const size_t row0 = (size_t)(b * LL + c * CLEN);
    const float* drow = delta + row0 * DINNER + d;
    const float* urow = xc + row0 * DINNER + d;
    const float* zrow = xz + row0 * (2 * DINNER) + DINNER + d;
    const float* bcrow = xdbl + row0 * 96 + 64;
    float* yrow = y + row0 * DINNER + d;

    for (int t = 0; t < CLEN; t++) {
        float dlt = drow[(size_t)t * DINNER];
        float u = urow[(size_t)t * DINNER];
        float du = dlt * u;
        const float4* bc = (const float4*)(bcrow + (size_t)t * 96);
        float Bv[DSTATE], Cv[DSTATE];
        float4 q;
        q = bc[0]; Bv[0] = q.x; Bv[1] = q.y; Bv[2] = q.z; Bv[3] = q.w;
        q = bc[1]; Bv[4] = q.x; Bv[5] = q.y; Bv[6] = q.z; Bv[7] = q.w;
        q = bc[2]; Bv[8] = q.x; Bv[9] = q.y; Bv[10] = q.z; Bv[11] = q.w;
        q = bc[3]; Bv[12] = q.x; Bv[13] = q.y; Bv[14] = q.z; Bv[15] = q.w;
        q = bc[4]; Cv[0] = q.x; Cv[1] = q.y; Cv[2] = q.z; Cv[3] = q.w;
        q = bc[5]; Cv[4] = q.x; Cv[5] = q.y; Cv[6] = q.z; Cv[7] = q.w;
        q = bc[6]; Cv[8] = q.x; Cv[9] = q.y; Cv[10] = q.z; Cv[11] = q.w;
        q = bc[7]; Cv[12] = q.x; Cv[13] = q.y; Cv[14] = q.z; Cv[15] = q.w;

        float acc = 0.0f;
#pragma unroll
        for (int n = 0; n < DSTATE; n++) {
            float a = __expf(dlt * A2[n]);
            h[n] = fmaf(a, h[n], du * Bv[n]);
            acc = fmaf(h[n], Cv[n], acc);
        }
        float z = zrow[(size_t)t * (2 * DINNER)];
        yrow[(size_t)t * DINNER] = (acc + u * Dd) * siluf(z);
    }
}

// ------------------------------- launcher -----------------------------------
extern "C" void kernel_launch(void* const* d_in, const int* in_sizes, int n_in,
                              void* d_out, int out_size)
{
    const float* x         = (const float*)d_in[0];
    const float* in_proj_w = (const float*)d_in[1];
    const float* conv_w    = (const float*)d_in[2];
    const float* conv_b    = (const float*)d_in[3];
    const float* x_proj_w  = (const float*)d_in[4];
    const float* dt_proj_w = (const float*)d_in[5];
    const float* dt_proj_b = (const float*)d_in[6];
    const float* A_log     = (const float*)d_in[7];
    const float* Dw        = (const float*)d_in[8];
    const float* ssm_out_w = (const float*)d_in[9];
    const float* final_w   = (const float*)d_in[10];
    const float* final_b   = (const float*)d_in[11];
    float* out = (float*)d_out;

    float *xz, *xc, *xdbl, *delta, *y, *mid, *P, *He, *Hi;
    cudaGetSymbolAddress((void**)&xz, g_xz);
    cudaGetSymbolAddress((void**)&xc, g_xc);
    cudaGetSymbolAddress((void**)&xdbl, g_xdbl);
    cudaGetSymbolAddress((void**)&delta, g_delta);
    cudaGetSymbolAddress((void**)&y, g_y);
    cudaGetSymbolAddress((void**)&mid, g_mid);
    cudaGetSymbolAddress((void**)&P, g_P);
    cudaGetSymbolAddress((void**)&He, g_He);
    cudaGetSymbolAddress((void**)&Hi, g_Hi);

    // 1. in_proj: (4096,1024) x (4096,1024)^T -> (4096,4096)
    gemm_nt<128, 128, 16, 8, 8, EPI_NONE><<<dim3(4096 / 128, BL / 128), 256>>>(
        x, DMODEL, in_proj_w, DMODEL, xz, 2 * DINNER,
        BL, 2 * DINNER, DMODEL, nullptr);

    // 2. causal depthwise conv + SiLU -> xc (4096,2048)
    conv_silu_kernel<<<dim3(DINNER / 256, LL / 8, BB), 256>>>(xz, conv_w, conv_b, xc);

    // 3. x_proj: (4096,2048) x (96,2048)^T -> (4096,96)   (small-N config)
    gemm_nt<32, 96, 16, 2, 6, EPI_NONE><<<dim3(1, BL / 32), 256>>>(
        xc, DINNER, x_proj_w, DINNER, xdbl, 96,
        BL, 96, DINNER, nullptr);

    // 4. dt_proj + softplus: (4096,64) x (2048,64)^T -> delta (4096,2048)
    gemm_nt<128, 128, 16, 8, 8, EPI_SOFTPLUS><<<dim3(DINNER / 128, BL / 128), 256>>>(
        xdbl, 96, dt_proj_w, DTRANK, delta, DINNER,
        BL, DINNER, DTRANK, dt_proj_b);

    // 5. chunked selective scan (fused D-skip + SiLU(z) gate) -> y
    scan_phaseA<<<dim3(DINNER / 256, NCHUNK, BB), 256>>>(delta, xc, xdbl, A_log, P, He);
    scan_phaseB<<<dim3((BB * DINNER * DSTATE) / 256), 256>>>(P, He, Hi);
    scan_phaseC<<<dim3(DINNER / 256, NCHUNK, BB), 256>>>(delta, xc, xdbl, A_log,
                                                         Dw, xz, Hi, y);

    // 6. out_proj: (4096,2048) x (1024,2048)^T -> mid (4096,1024)
    gemm_nt<128, 128, 16, 8, 8, EPI_NONE><<<dim3(DMODEL / 128, BL / 128), 256>>>(
        y, DINNER, ssm_out_w, DINNER, mid, DMODEL,
        BL, DMODEL, DINNER, nullptr);

    // 7. final linear + bias + SiLU -> d_out (4096,1024)
    gemm_nt<128, 128, 16, 8, 8, EPI_SILU><<<dim3(DMODEL / 128, BL / 128), 256>>>(
        mid, DMODEL, final_w, DMODEL, out, DMODEL,
        BL, DMODEL, DMODEL, final_b);
}

// round 4
// speedup vs baseline: 1.0069x; 1.0069x over previous
#include <cuda_runtime.h>
#include <cuda_bf16.h>
#include <math.h>

// ---------------------------------------------------------------------------
// MambaSSMBlock: B=2, L=2048, D_MODEL=1024, D_INNER=2048, D_STATE=16,
// D_CONV=4, DT_RANK=64.  BL = 4096 rows.
//
// R3 change: GEMM inner loop uses packed fma.rn.f32x2 (FFMA2) — 2 FMAs per
// fma-pipe slot, doubling the fp32 ceiling. Bitwise-identical rounding vs
// scalar fmaf, so correctness is unchanged.
// ---------------------------------------------------------------------------

#define BB 2
#define LL 2048
#define DMODEL 1024
#define DINNER 2048
#define DSTATE 16
#define DTRANK 64
#define BL (BB * LL)
#define NCHUNK 16
#define CLEN (LL / NCHUNK)   // 128

// ------------------------- scratch (device globals) ------------------------
__device__ float g_xz[(size_t)BL * 2 * DINNER];     // 4096 x 4096
__device__ float g_xc[(size_t)BL * DINNER];         // 4096 x 2048
__device__ float g_xdbl[(size_t)BL * 96];           // 4096 x 96
__device__ float g_delta[(size_t)BL * DINNER];      // 4096 x 2048
__device__ float g_y[(size_t)BL * DINNER];          // 4096 x 2048
__device__ float g_mid[(size_t)BL * DMODEL];        // 4096 x 1024
__device__ float g_P[(size_t)BB * DINNER * NCHUNK * DSTATE];
__device__ float g_He[(size_t)BB * DINNER * NCHUNK * DSTATE];
__device__ float g_Hi[(size_t)BB * DINNER * NCHUNK * DSTATE];

// ------------------------------ helpers ------------------------------------
__device__ __forceinline__ float siluf(float x) {
    return x / (1.0f + __expf(-x));
}
__device__ __forceinline__ float softplusf(float x) {
    return (x > 20.0f) ? x : log1pf(__expf(x));
}

enum { EPI_NONE = 0, EPI_SOFTPLUS = 1, EPI_SILU = 2 };

// packed f32x2 helpers
__device__ __forceinline__ unsigned long long pack_dup_f32(float a) {
    unsigned long long r;
    asm("mov.b64 %0, {%1, %1};" : "=l"(r) : "f"(a));
    return r;
}
__device__ __forceinline__ void fma2(unsigned long long& d,
                                     unsigned long long a,
                                     unsigned long long b) {
    asm("fma.rn.f32x2 %0, %1, %2, %0;" : "+l"(d) : "l"(a), "l"(b));
}
__device__ __forceinline__ void unpack2(float& lo, float& hi, unsigned long long v) {
    asm("mov.b64 {%0, %1}, %2;" : "=f"(lo), "=f"(hi) : "l"(v));
}

// ------------------------------ generic GEMM --------------------------------
// C[M,N] = A[M,K] * B[N,K]^T  (+ bias + activation epilogue)
// A row-major lda, B row-major ldb (weights are (out_features, in_features)),
// C row-major ldc.  M must be a multiple of BM; N may be ragged.
// TN must be even (accumulators are f32x2 pairs along N).
template <int BM, int BN, int BK, int TM, int TN, int EPI>
__global__ void __launch_bounds__((BM / TM) * (BN / TN), 2)
gemm_nt(const float* __restrict__ A, int lda,
        const float* __restrict__ B, int ldb,
        float* __restrict__ C, int ldc,
        int M, int N, int K,
        const float* __restrict__ bias)
{
    constexpr int NT = (BM / TM) * (BN / TN);
    constexpr int TNH = TN / 2;
    __shared__ float As[BK][BM];
    __shared__ float Bs[BK][BN];

    const int tid = threadIdx.x;
    const int tx = tid % (BN / TN);
    const int ty = tid / (BN / TN);
    const int m0 = blockIdx.y * BM;
    const int n0 = blockIdx.x * BN;

    unsigned long long acc[TM][TNH];
#pragma unroll
    for (int i = 0; i < TM; i++)
#pragma unroll
        for (int j = 0; j < TNH; j++) acc[i][j] = 0ULL;

    for (int k0 = 0; k0 < K; k0 += BK) {
        // cooperative load of A tile (stored transposed: As[k][m])
        for (int i = tid * 4; i < BM * BK; i += NT * 4) {
            int r = i / BK, c = i % BK;
            float4 v = *(const float4*)(A + (size_t)(m0 + r) * lda + k0 + c);
            As[c + 0][r] = v.x; As[c + 1][r] = v.y;
            As[c + 2][r] = v.z; As[c + 3][r] = v.w;
        }
        // cooperative load of B tile (Bs[k][n]) with N guard
        for (int i = tid * 4; i < BN * BK; i += NT * 4) {
            int r = i / BK, c = i % BK;
            int gn = n0 + r;
            float4 v = make_float4(0.f, 0.f, 0.f, 0.f);
            if (gn < N) v = *(const float4*)(B + (size_t)gn * ldb + k0 + c);
            Bs[c + 0][r] = v.x; Bs[c + 1][r] = v.y;
            Bs[c + 2][r] = v.z; Bs[c + 3][r] = v.w;
        }
        __syncthreads();

#pragma unroll
        for (int kk = 0; kk < BK; kk++) {
            unsigned long long a2[TM], b2[TNH];
#pragma unroll
            for (int i = 0; i < TM; i++)
                a2[i] = pack_dup_f32(As[kk][ty * TM + i]);
#pragma unroll
            for (int j = 0; j < TNH; j++)
                b2[j] = *(const unsigned long long*)&Bs[kk][tx * TN + 2 * j];
#pragma unroll
            for (int i = 0; i < TM; i++)
#pragma unroll
                for (int j = 0; j < TNH; j++)
                    fma2(acc[i][j], a2[i], b2[j]);
        }
        __syncthreads();
    }

#pragma unroll
    for (int i = 0; i < TM; i++) {
        int m = m0 + ty * TM + i;
#pragma unroll
        for (int j = 0; j < TNH; j++) {
            float vlo, vhi;
            unpack2(vlo, vhi, acc[i][j]);
            int n = n0 + tx * TN + 2 * j;
#pragma unroll
            for (int s = 0; s < 2; s++) {
                int nn = n + s;
                if (nn < N) {
                    float v = (s == 0) ? vlo : vhi;
                    if (EPI == EPI_SOFTPLUS) v = softplusf(v + bias[nn]);
                    else if (EPI == EPI_SILU) v = siluf(v + bias[nn]);
                    C[(size_t)m * ldc + nn] = v;
                }
            }
        }
    }
}

// ------------------------ conv1d (causal depthwise) + SiLU ------------------
// xin = g_xz[:, 0:DINNER].  Each thread handles 8 consecutive l for one d.
__global__ void __launch_bounds__(256)
conv_silu_kernel(const float* __restrict__ xz,
                 const float* __restrict__ conv_w,
                 const float* __restrict__ conv_b,
                 float* __restrict__ xc)
{
    const int d = blockIdx.x * 256 + threadIdx.x;     // 0..2047
    const int l0 = blockIdx.y * 8;                    // 0..2040
    const int b = blockIdx.z;

    const float w0 = conv_w[d * 4 + 0];
    const float w1 = conv_w[d * 4 + 1];
    const float w2 = conv_w[d * 4 + 2];
    const float w3 = conv_w[d * 4 + 3];
    const float cb = conv_b[d];

    float xv[11];
#pragma unroll
    for (int j = 0; j < 11; j++) {
        int l = l0 - 3 + j;
        xv[j] = (l >= 0) ? xz[((size_t)(b * LL + l)) * (2 * DINNER) + d] : 0.0f;
    }
#pragma unroll
    for (int i = 0; i < 8; i++) {
        float s = w0 * xv[i] + w1 * xv[i + 1] + w2 * xv[i + 2] + w3 * xv[i + 3] + cb;
        xc[((size_t)(b * LL + l0 + i)) * DINNER + d] = siluf(s);
    }
}

// ------------------------ selective scan: 3-phase chunked -------------------
// Phase A: per (b, d, chunk): local scan with h0=0; record per-state decay
// product P[n] = prod_t exp(delta_t * A[n]) and local end-state h_end[n].
__global__ void __launch_bounds__(256)
scan_phaseA(const float* __restrict__ delta,
            const float* __restrict__ xc,
            const float* __restrict__ xdbl,
            const float* __restrict__ A_log,
            float* __restrict__ Pout,
            float* __restrict__ Hend)
{
    const int d = blockIdx.x * 256 + threadIdx.x;
    const int c = blockIdx.y;
    const int b = blockIdx.z;

    float A2[DSTATE], h[DSTATE], P[DSTATE];
#pragma unroll
    for (int n = 0; n < DSTATE; n++) {
        A2[n] = -__expf(A_log[d * DSTATE + n]);
        h[n] = 0.0f;
        P[n] = 1.0f;
    }

    const size_t row0 = (size_t)(b * LL + c * CLEN);
    const float* drow = delta + row0 * DINNER + d;
    const float* urow = xc + row0 * DINNER + d;
    const float* bcrow = xdbl + row0 * 96 + 64;   // B_t at +64, C_t at +80

    for (int t = 0; t < CLEN; t++) {
        float dlt = drow[(size_t)t * DINNER];
        float du = dlt * urow[(size_t)t * DINNER];
        const float4* bc = (const float4*)(bcrow + (size_t)t * 96);
        float Bv[DSTATE];
        float4 q;
        q = bc[0]; Bv[0] = q.x; Bv[1] = q.y; Bv[2] = q.z; Bv[3] = q.w;
        q = bc[1]; Bv[4] = q.x; Bv[5] = q.y; Bv[6] = q.z; Bv[7] = q.w;
        q = bc[2]; Bv[8] = q.x; Bv[9] = q.y; Bv[10] = q.z; Bv[11] = q.w;
        q = bc[3]; Bv[12] = q.x; Bv[13] = q.y; Bv[14] = q.z; Bv[15] = q.w;
#pragma unroll
        for (int n = 0; n < DSTATE; n++) {
            float a = __expf(dlt * A2[n]);
            P[n] *= a;
            h[n] = fmaf(a, h[n], du * Bv[n]);
        }
    }
    const size_t o = (((size_t)(b * DINNER + d)) * NCHUNK + c) * DSTATE;
#pragma unroll
    for (int n = 0; n < DSTATE; n++) {
        Pout[o + n] = P[n];
        Hend[o + n] = h[n];
    }
}

// Phase B: serial combine over the 16 chunks; one thread per (b, d, n).
__global__ void __launch_bounds__(256)
scan_phaseB(const float* __restrict__ P,
            const float* __restrict__ He,
            float* __restrict__ Hi)
{
    const int idx = blockIdx.x * 256 + threadIdx.x;   // 0 .. B*DINNER*DSTATE-1
    const int n = idx % DSTATE;
    const int bd = idx / DSTATE;
    float h = 0.0f;
    for (int c = 0; c < NCHUNK; c++) {
        const size_t o = (((size_t)bd) * NCHUNK + c) * DSTATE + n;
        Hi[o] = h;
        h = P[o] * h + He[o];
    }
}

// Phase C: rerun each chunk from the corrected initial state; emit
// y = (sum_n h[n]*C[n] + u*D) * SiLU(z), fully fused.
__global__ void __launch_bounds__(256)
scan_phaseC(const float* __restrict__ delta,
            const float* __restrict__ xc,
            const float* __restrict__ xdbl,
            const float* __restrict__ A_log,
            const float* __restrict__ Dw,
            const float* __restrict__ xz,
            const float* __restrict__ Hi,
            float* __restrict__ y)
{
    const int d = blockIdx.x * 256 + threadIdx.x;
    const int c = blockIdx.y;
    const int b = blockIdx.z;

    float A2[DSTATE], h[DSTATE];
    const size_t ho = (((size_t)(b * DINNER + d)) * NCHUNK + c) * DSTATE;
#pragma unroll
    for (int n = 0; n < DSTATE; n++) {
        A2[n] = -__expf(A_log[d * DSTATE + n]);
        h[n] = Hi[ho + n];
    }
    const float Dd = Dw[d];

    const size_t row0 = (size_t)(b * LL + c * CLEN);
    const float* drow = delta + row0 * DINNER + d;
    const float* urow = xc + row0 * DINNER + d;
    const float* zrow = xz + row0 * (2 * DINNER) + DINNER + d;
    const float* bcrow = xdbl + row0 * 96 + 64;
    float* yrow = y + row0 * DINNER + d;

    for (int t = 0; t < CLEN; t++) {
        float dlt = drow[(size_t)t * DINNER];
        float u = urow[(size_t)t * DINNER];
        float du = dlt * u;
        const float4* bc = (const float4*)(bcrow + (size_t)t * 96);
        float Bv[DSTATE], Cv[DSTATE];
        float4 q;
        q = bc[0]; Bv[0] = q.x; Bv[1] = q.y; Bv[2] = q.z; Bv[3] = q.w;
        q = bc[1]; Bv[4] = q.x; Bv[5] = q.y; Bv[6] = q.z; Bv[7] = q.w;
        q = bc[2]; Bv[8] = q.x; Bv[9] = q.y; Bv[10] = q.z; Bv[11] = q.w;
        q = bc[3]; Bv[12] = q.x; Bv[13] = q.y; Bv[14] = q.z; Bv[15] = q.w;
        q = bc[4]; Cv[0] = q.x; Cv[1] = q.y; Cv[2] = q.z; Cv[3] = q.w;
        q = bc[5]; Cv[4] = q.x; Cv[5] = q.y; Cv[6] = q.z; Cv[7] = q.w;
        q = bc[6]; Cv[8] = q.x; Cv[9] = q.y; Cv[10] = q.z; Cv[11] = q.w;
        q = bc[7]; Cv[12] = q.x; Cv[13] = q.y; Cv[14] = q.z; Cv[15] = q.w;

        float acc = 0.0f;
#pragma unroll
        for (int n = 0; n < DSTATE; n++) {
            float a = __expf(dlt * A2[n]);
            h[n] = fmaf(a, h[n], du * Bv[n]);
            acc = fmaf(h[n], Cv[n], acc);
        }
        float z = zrow[(size_t)t * (2 * DINNER)];
        yrow[(size_t)t * DINNER] = (acc + u * Dd) * siluf(z);
    }
}

// ------------------------------- launcher -----------------------------------
extern "C" void kernel_launch(void* const* d_in, const int* in_sizes, int n_in,
                              void* d_out, int out_size)
{
    const float* x         = (const float*)d_in[0];
    const float* in_proj_w = (const float*)d_in[1];
    const float* conv_w    = (const float*)d_in[2];
    const float* conv_b    = (const float*)d_in[3];
    const float* x_proj_w  = (const float*)d_in[4];
    const float* dt_proj_w = (const float*)d_in[5];
    const float* dt_proj_b = (const float*)d_in[6];
    const float* A_log     = (const float*)d_in[7];
    const float* Dw        = (const float*)d_in[8];
    const float* ssm_out_w = (const float*)d_in[9];
    const float* final_w   = (const float*)d_in[10];
    const float* final_b   = (const float*)d_in[11];
    float* out = (float*)d_out;

    float *xz, *xc, *xdbl, *delta, *y, *mid, *P, *He, *Hi;
    cudaGetSymbolAddress((void**)&xz, g_xz);
    cudaGetSymbolAddress((void**)&xc, g_xc);
    cudaGetSymbolAddress((void**)&xdbl, g_xdbl);
    cudaGetSymbolAddress((void**)&delta, g_delta);
    cudaGetSymbolAddress((void**)&y, g_y);
    cudaGetSymbolAddress((void**)&mid, g_mid);
    cudaGetSymbolAddress((void**)&P, g_P);
    cudaGetSymbolAddress((void**)&He, g_He);
    cudaGetSymbolAddress((void**)&Hi, g_Hi);

    // 1. in_proj: (4096,1024) x (4096,1024)^T -> (4096,4096)
    gemm_nt<128, 128, 16, 8, 8, EPI_NONE><<<dim3(4096 / 128, BL / 128), 256>>>(
        x, DMODEL, in_proj_w, DMODEL, xz, 2 * DINNER,
        BL, 2 * DINNER, DMODEL, nullptr);

    // 2. causal depthwise conv + SiLU -> xc (4096,2048)
    conv_silu_kernel<<<dim3(DINNER / 256, LL / 8, BB), 256>>>(xz, conv_w, conv_b, xc);

    // 3. x_proj: (4096,2048) x (96,2048)^T -> (4096,96)   (small-N config)
    gemm_nt<32, 96, 16, 2, 6, EPI_NONE><<<dim3(1, BL / 32), 256>>>(
        xc, DINNER, x_proj_w, DINNER, xdbl, 96,
        BL, 96, DINNER, nullptr);

    // 4. dt_proj + softplus: (4096,64) x (2048,64)^T -> delta (4096,2048)
    gemm_nt<128, 128, 16, 8, 8, EPI_SOFTPLUS><<<dim3(DINNER / 128, BL / 128), 256>>>(
        xdbl, 96, dt_proj_w, DTRANK, delta, DINNER,
        BL, DINNER, DTRANK, dt_proj_b);

    // 5. chunked selective scan (fused D-skip + SiLU(z) gate) -> y
    scan_phaseA<<<dim3(DINNER / 256, NCHUNK, BB), 256>>>(delta, xc, xdbl, A_log, P, He);
    scan_phaseB<<<dim3((BB * DINNER * DSTATE) / 256), 256>>>(P, He, Hi);
    scan_phaseC<<<dim3(DINNER / 256, NCHUNK, BB), 256>>>(delta, xc, xdbl, A_log,
                                                         Dw, xz, Hi, y);

    // 6. out_proj: (4096,2048) x (1024,2048)^T -> mid (4096,1024)
    gemm_nt<128, 128, 16, 8, 8, EPI_NONE><<<dim3(DMODEL / 128, BL / 128), 256>>>(
        y, DINNER, ssm_out_w, DINNER, mid, DMODEL,
        BL, DMODEL, DINNER, nullptr);

    // 7. final linear + bias + SiLU -> d_out (4096,1024)
    gemm_nt<128, 128, 16, 8, 8, EPI_SILU><<<dim3(DMODEL / 128, BL / 128), 256>>>(
        mid, DMODEL, final_w, DMODEL, out, DMODEL,
        BL, DMODEL, DMODEL, final_b);
}

// round 7
// speedup vs baseline: 2.2227x; 2.2075x over previous
#include <cuda_runtime.h>
#include <cuda_bf16.h>
#include <cstdint>
#include <math.h>

// ---------------------------------------------------------------------------
// MambaSSMBlock on GB300 (harness PTX target = sm_103 plain, so NO tcgen05).
// GEMMs: warp-level HMMA mma.sync bf16 with 3-pass hi/lo fp32-split,
// in-kernel conversion (fp32 global -> bf16 hi/lo smem tiles).
// ---------------------------------------------------------------------------

#define BB 2
#define LL 2048
#define DMODEL 1024
#define DINNER 2048
#define DSTATE 16
#define DTRANK 64
#define BL (BB * LL)
#define NCHUNK 16
#define CLEN (LL / NCHUNK)   // 128

// ------------------------- scratch (device globals) ------------------------
__device__ float g_xz[(size_t)BL * 2 * DINNER];     // 4096 x 4096
__device__ float g_xc[(size_t)BL * DINNER];         // 4096 x 2048
__device__ float g_xdbl[(size_t)BL * 96];           // 4096 x 96
__device__ float g_delta[(size_t)BL * DINNER];      // 4096 x 2048
__device__ float g_y[(size_t)BL * DINNER];          // 4096 x 2048
__device__ float g_mid[(size_t)BL * DMODEL];        // 4096 x 1024
__device__ float g_P[(size_t)BB * DINNER * NCHUNK * DSTATE];
__device__ float g_He[(size_t)BB * DINNER * NCHUNK * DSTATE];
__device__ float g_Hi[(size_t)BB * DINNER * NCHUNK * DSTATE];

// ------------------------------ helpers ------------------------------------
__device__ __forceinline__ float siluf(float x) {
    return x / (1.0f + __expf(-x));
}
__device__ __forceinline__ float softplusf(float x) {
    return (x > 20.0f) ? x : log1pf(__expf(x));
}

enum { EPI_NONE = 0, EPI_SOFTPLUS = 1, EPI_SILU = 2 };

// --------------------------- HMMA primitives --------------------------------
__device__ __forceinline__ void ldsm4(uint32_t* r, uint32_t addr) {
    asm volatile("ldmatrix.sync.aligned.m8n8.x4.shared.b16 {%0,%1,%2,%3}, [%4];"
                 : "=r"(r[0]), "=r"(r[1]), "=r"(r[2]), "=r"(r[3]) : "r"(addr));
}
__device__ __forceinline__ void ldsm2(uint32_t* r, uint32_t addr) {
    asm volatile("ldmatrix.sync.aligned.m8n8.x2.shared.b16 {%0,%1}, [%2];"
                 : "=r"(r[0]), "=r"(r[1]) : "r"(addr));
}
__device__ __forceinline__ void mma_bf16(float* c, const uint32_t* a, const uint32_t* b) {
    asm volatile(
        "mma.sync.aligned.m16n8k16.row.col.f32.bf16.bf16.f32 "
        "{%0,%1,%2,%3}, {%4,%5,%6,%7}, {%8,%9}, {%0,%1,%2,%3};"
        : "+f"(c[0]), "+f"(c[1]), "+f"(c[2]), "+f"(c[3])
        : "r"(a[0]), "r"(a[1]), "r"(a[2]), "r"(a[3]), "r"(b[0]), "r"(b[1]));
}

// ---------------------------- HMMA split GEMM -------------------------------
// C[M,N] = A[M,K] * B[N,K]^T (+bias+activation), fp32 in/out.
// Internally: A,B split into bf16 hi/lo; 3 passes hi*hi + hi*lo + lo*hi.
// BM=BN=128, BK=32, 256 threads (8 warps as 2x4, warp tile 64x32).
// M % 128 == 0, K % 32 == 0, N ragged (load/store guards).
#define SPAD 40   // bf16 row stride (32 data + 8 pad) -> conflict-free ldmatrix

template <int EPI>
__global__ void __launch_bounds__(256)
hmma_gemm(const float* __restrict__ A, int lda,
          const float* __restrict__ B, int ldb,
          float* __restrict__ C, int ldc,
          int N, int K, const float* __restrict__ bias)
{
    __shared__ __nv_bfloat16 sAhi[128 * SPAD];
    __shared__ __nv_bfloat16 sAlo[128 * SPAD];
    __shared__ __nv_bfloat16 sBhi[128 * SPAD];
    __shared__ __nv_bfloat16 sBlo[128 * SPAD];

    const int tid = threadIdx.x;
    const int wid = tid >> 5;
    const int lane = tid & 31;
    const int m0 = blockIdx.y * 128;
    const int n0 = blockIdx.x * 128;
    const int wm = (wid >> 2) * 64;   // warp row offset (0 or 64)
    const int wn = (wid & 3) * 32;    // warp col offset (0,32,64,96)

    const uint32_t baseAhi = (uint32_t)__cvta_generic_to_shared(sAhi);
    const uint32_t baseAlo = (uint32_t)__cvta_generic_to_shared(sAlo);
    const uint32_t baseBhi = (uint32_t)__cvta_generic_to_shared(sBhi);
    const uint32_t baseBlo = (uint32_t)__cvta_generic_to_shared(sBlo);

    float acc[4][4][4];
#pragma unroll
    for (int i = 0; i < 4; i++)
#pragma unroll
        for (int j = 0; j < 4; j++)
#pragma unroll
            for (int k = 0; k < 4; k++) acc[i][j][k] = 0.0f;

    // per-lane ldmatrix address offsets (in elements)
    const int aoff = (lane & 15) * SPAD + (lane >> 4) * 8;           // x4
    const int boff = (lane & 7) * SPAD + ((lane >> 3) & 1) * 8;      // x2

    for (int k0 = 0; k0 < K; k0 += 32) {
        // ---- fill smem: load fp32, split to bf16 hi/lo ----
        // A tile: 128 x 32 floats = 1024 float4, 4 per thread
#pragma unroll
        for (int it = 0; it < 4; it++) {
            int i = tid + it * 256;
            int r = i >> 3;              // 8 float4 per row
            int c = (i & 7) * 4;
            float4 v = *(const float4*)(A + (size_t)(m0 + r) * lda + k0 + c);
            __nv_bfloat16 h0 = __float2bfloat16(v.x);
            __nv_bfloat16 h1 = __float2bfloat16(v.y);
            __nv_bfloat16 h2 = __float2bfloat16(v.z);
            __nv_bfloat16 h3 = __float2bfloat16(v.w);
            __nv_bfloat16 l0 = __float2bfloat16(v.x - __bfloat162float(h0));
            __nv_bfloat16 l1 = __float2bfloat16(v.y - __bfloat162float(h1));
            __nv_bfloat16 l2 = __float2bfloat16(v.z - __bfloat162float(h2));
            __nv_bfloat16 l3 = __float2bfloat16(v.w - __bfloat162float(h3));
            __nv_bfloat162* ph = (__nv_bfloat162*)&sAhi[r * SPAD + c];
            __nv_bfloat162* pl = (__nv_bfloat162*)&sAlo[r * SPAD + c];
            ph[0] = __nv_bfloat162(h0, h1); ph[1] = __nv_bfloat162(h2, h3);
            pl[0] = __nv_bfloat162(l0, l1); pl[1] = __nv_bfloat162(l2, l3);
        }
        // B tile with row guard
#pragma unroll
        for (int it = 0; it < 4; it++) {
            int i = tid + it * 256;
            int r = i >> 3;
            int c = (i & 7) * 4;
            int gn = n0 + r;
            float4 v = make_float4(0.f, 0.f, 0.f, 0.f);
            if (gn < N) v = *(const float4*)(B + (size_t)gn * ldb + k0 + c);
            __nv_bfloat16 h0 = __float2bfloat16(v.x);
            __nv_bfloat16 h1 = __float2bfloat16(v.y);
            __nv_bfloat16 h2 = __float2bfloat16(v.z);
            __nv_bfloat16 h3 = __float2bfloat16(v.w);
            __nv_bfloat16 l0 = __float2bfloat16(v.x - __bfloat162float(h0));
            __nv_bfloat16 l1 = __float2bfloat16(v.y - __bfloat162float(h1));
            __nv_bfloat16 l2 = __float2bfloat16(v.z - __bfloat162float(h2));
            __nv_bfloat16 l3 = __float2bfloat16(v.w - __bfloat162float(h3));
            __nv_bfloat162* ph = (__nv_bfloat162*)&sBhi[r * SPAD + c];
            __nv_bfloat162* pl = (__nv_bfloat162*)&sBlo[r * SPAD + c];
            ph[0] = __nv_bfloat162(h0, h1); ph[1] = __nv_bfloat162(h2, h3);
            pl[0] = __nv_bfloat162(l0, l1); pl[1] = __nv_bfloat162(l2, l3);
        }
        __syncthreads();

        // ---- compute: 2 k16 halves x 3 passes ----
#pragma unroll
        for (int kh = 0; kh < 2; kh++) {
            uint32_t af[4][4], bf[4][2];
            const uint32_t ka = (uint32_t)(kh * 16) * 2;   // byte offset in row

            // pass 1: Ahi * Bhi
#pragma unroll
            for (int mi = 0; mi < 4; mi++)
                ldsm4(af[mi], baseAhi + ((wm + mi * 16) * SPAD + aoff) * 2 + ka);
#pragma unroll
            for (int ni = 0; ni < 4; ni++)
                ldsm2(bf[ni], baseBhi + ((wn + ni * 8) * SPAD + boff) * 2 + ka);
#pragma unroll
            for (int mi = 0; mi < 4; mi++)
#pragma unroll
                for (int ni = 0; ni < 4; ni++)
                    mma_bf16(acc[mi][ni], af[mi], bf[ni]);

            // pass 2: Ahi * Blo (reuse af)
#pragma unroll
            for (int ni = 0; ni < 4; ni++)
                ldsm2(bf[ni], baseBlo + ((wn + ni * 8) * SPAD + boff) * 2 + ka);
#pragma unroll
            for (int mi = 0; mi < 4; mi++)
#pragma unroll
                for (int ni = 0; ni < 4; ni++)
                    mma_bf16(acc[mi][ni], af[mi], bf[ni]);

            // pass 3: Alo * Bhi
#pragma unroll
            for (int mi = 0; mi < 4; mi++)
                ldsm4(af[mi], baseAlo + ((wm + mi * 16) * SPAD + aoff) * 2 + ka);
#pragma unroll
            for (int ni = 0; ni < 4; ni++)
                ldsm2(bf[ni], baseBhi + ((wn + ni * 8) * SPAD + boff) * 2 + ka);
#pragma unroll
            for (int mi = 0; mi < 4; mi++)
#pragma unroll
                for (int ni = 0; ni < 4; ni++)
                    mma_bf16(acc[mi][ni], af[mi], bf[ni]);
        }
        __syncthreads();
    }

    // ---- epilogue ----
    const int tg = lane >> 2;            // row group 0..7
    const int tc = (lane & 3) * 2;       // col pair
#pragma unroll
    for (int mi = 0; mi < 4; mi++) {
#pragma unroll
        for (int ni = 0; ni < 4; ni++) {
#pragma unroll
            for (int h = 0; h < 2; h++) {          // c01 vs c23 (row +8)
                int m = m0 + wm + mi * 16 + tg + h * 8;
#pragma unroll
                for (int s = 0; s < 2; s++) {
                    int n = n0 + wn + ni * 8 + tc + s;
                    if (n < N) {
                        float v = acc[mi][ni][h * 2 + s];
                        if (EPI == EPI_SOFTPLUS) v = softplusf(v + bias[n]);
                        else if (EPI == EPI_SILU) v = siluf(v + bias[n]);
                        C[(size_t)m * ldc + n] = v;
                    }
                }
            }
        }
    }
}

// ------------------------ conv1d (causal depthwise) + SiLU ------------------
__global__ void __launch_bounds__(256)
conv_silu_kernel(const float* __restrict__ xz,
                 const float* __restrict__ conv_w,
                 const float* __restrict__ conv_b,
                 float* __restrict__ xc)
{
    const int d = blockIdx.x * 256 + threadIdx.x;     // 0..2047
    const int l0 = blockIdx.y * 8;                    // 0..2040
    const int b = blockIdx.z;

    const float w0 = conv_w[d * 4 + 0];
    const float w1 = conv_w[d * 4 + 1];
    const float w2 = conv_w[d * 4 + 2];
    const float w3 = conv_w[d * 4 + 3];
    const float cb = conv_b[d];

    float xv[11];
#pragma unroll
    for (int j = 0; j < 11; j++) {
        int l = l0 - 3 + j;
        xv[j] = (l >= 0) ? xz[((size_t)(b * LL + l)) * (2 * DINNER) + d] : 0.0f;
    }
#pragma unroll
    for (int i = 0; i < 8; i++) {
        float s = w0 * xv[i] + w1 * xv[i + 1] + w2 * xv[i + 2] + w3 * xv[i + 3] + cb;
        xc[((size_t)(b * LL + l0 + i)) * DINNER + d] = siluf(s);
    }
}

// ------------------------ selective scan: 3-phase chunked -------------------
__global__ void __launch_bounds__(256)
scan_phaseA(const float* __restrict__ delta,
            const float* __restrict__ xc,
            const float* __restrict__ xdbl,
            const float* __restrict__ A_log,
            float* __restrict__ Pout,
            float* __restrict__ Hend)
{
    const int d = blockIdx.x * 256 + threadIdx.x;
    const int c = blockIdx.y;
    const int b = blockIdx.z;

    float A2[DSTATE], h[DSTATE], P[DSTATE];
#pragma unroll
    for (int n = 0; n < DSTATE; n++) {
        A2[n] = -__expf(A_log[d * DSTATE + n]);
        h[n] = 0.0f;
        P[n] = 1.0f;
    }

    const size_t row0 = (size_t)(b * LL + c * CLEN);
    const float* drow = delta + row0 * DINNER + d;
    const float* urow = xc + row0 * DINNER + d;
    const float* bcrow = xdbl + row0 * 96 + 64;

    for (int t = 0; t < CLEN; t++) {
        float dlt = drow[(size_t)t * DINNER];
        float du = dlt * urow[(size_t)t * DINNER];
        const float4* bc = (const float4*)(bcrow + (size_t)t * 96);
        float Bv[DSTATE];
        float4 q;
        q = bc[0]; Bv[0] = q.x; Bv[1] = q.y; Bv[2] = q.z; Bv[3] = q.w;
        q = bc[1]; Bv[4] = q.x; Bv[5] = q.y; Bv[6] = q.z; Bv[7] = q.w;
        q = bc[2]; Bv[8] = q.x; Bv[9] = q.y; Bv[10] = q.z; Bv[11] = q.w;
        q = bc[3]; Bv[12] = q.x; Bv[13] = q.y; Bv[14] = q.z; Bv[15] = q.w;
#pragma unroll
        for (int n = 0; n < DSTATE; n++) {
            float a = __expf(dlt * A2[n]);
            P[n] *= a;
            h[n] = fmaf(a, h[n], du * Bv[n]);
        }
    }
    const size_t o = (((size_t)(b * DINNER + d)) * NCHUNK + c) * DSTATE;
#pragma unroll
    for (int n = 0; n < DSTATE; n++) {
        Pout[o + n] = P[n];
        Hend[o + n] = h[n];
    }
}

__global__ void __launch_bounds__(256)
scan_phaseB(const float* __restrict__ P,
            const float* __restrict__ He,
            float* __restrict__ Hi)
{
    const int idx = blockIdx.x * 256 + threadIdx.x;
    const int n = idx % DSTATE;
    const int bd = idx / DSTATE;
    float h = 0.0f;
    for (int c = 0; c < NCHUNK; c++) {
        const size_t o = (((size_t)bd) * NCHUNK + c) * DSTATE + n;
        Hi[o] = h;
        h = P[o] * h + He[o];
    }
}

__global__ void __launch_bounds__(256)
scan_phaseC(const float* __restrict__ delta,
            const float* __restrict__ xc,
            const float* __restrict__ xdbl,
            const float* __restrict__ A_log,
            const float* __restrict__ Dw,
            const float* __restrict__ xz,
            const float* __restrict__ Hi,
            float* __restrict__ y)
{
    const int d = blockIdx.x * 256 + threadIdx.x;
    const int c = blockIdx.y;
    const int b = blockIdx.z;

    float A2[DSTATE], h[DSTATE];
    const size_t ho = (((size_t)(b * DINNER + d)) * NCHUNK + c) * DSTATE;
#pragma unroll
    for (int n = 0; n < DSTATE; n++) {
        A2[n] = -__expf(A_log[d * DSTATE + n]);
        h[n] = Hi[ho + n];
    }
    const float Dd = Dw[d];

    const size_t row0 = (size_t)(b * LL + c * CLEN);
    const float* drow = delta + row0 * DINNER + d;
    const float* urow = xc + row0 * DINNER + d;
    const float* zrow = xz + row0 * (2 * DINNER) + DINNER + d;
    const float* bcrow = xdbl + row0 * 96 + 64;
    float* yrow = y + row0 * DINNER + d;

    for (int t = 0; t < CLEN; t++) {
        float dlt = drow[(size_t)t * DINNER];
        float u = urow[(size_t)t * DINNER];
        float du = dlt * u;
        const float4* bc = (const float4*)(bcrow + (size_t)t * 96);
        float Bv[DSTATE], Cv[DSTATE];
        float4 q;
        q = bc[0]; Bv[0] = q.x; Bv[1] = q.y; Bv[2] = q.z; Bv[3] = q.w;
        q = bc[1]; Bv[4] = q.x; Bv[5] = q.y; Bv[6] = q.z; Bv[7] = q.w;
        q = bc[2]; Bv[8] = q.x; Bv[9] = q.y; Bv[10] = q.z; Bv[11] = q.w;
        q = bc[3]; Bv[12] = q.x; Bv[13] = q.y; Bv[14] = q.z; Bv[15] = q.w;
        q = bc[4]; Cv[0] = q.x; Cv[1] = q.y; Cv[2] = q.z; Cv[3] = q.w;
        q = bc[5]; Cv[4] = q.x; Cv[5] = q.y; Cv[6] = q.z; Cv[7] = q.w;
        q = bc[6]; Cv[8] = q.x; Cv[9] = q.y; Cv[10] = q.z; Cv[11] = q.w;
        q = bc[7]; Cv[12] = q.x; Cv[13] = q.y; Cv[14] = q.z; Cv[15] = q.w;

        float acc = 0.0f;
#pragma unroll
        for (int n = 0; n < DSTATE; n++) {
            float a = __expf(dlt * A2[n]);
            h[n] = fmaf(a, h[n], du * Bv[n]);
            acc = fmaf(h[n], Cv[n], acc);
        }
        float z = zrow[(size_t)t * (2 * DINNER)];
        yrow[(size_t)t * DINNER] = (acc + u * Dd) * siluf(z);
    }
}

// ------------------------------- launcher -----------------------------------
extern "C" void kernel_launch(void* const* d_in, const int* in_sizes, int n_in,
                              void* d_out, int out_size)
{
    const float* x         = (const float*)d_in[0];
    const float* in_proj_w = (const float*)d_in[1];
    const float* conv_w    = (const float*)d_in[2];
    const float* conv_b    = (const float*)d_in[3];
    const float* x_proj_w  = (const float*)d_in[4];
    const float* dt_proj_w = (const float*)d_in[5];
    const float* dt_proj_b = (const float*)d_in[6];
    const float* A_log     = (const float*)d_in[7];
    const float* Dw        = (const float*)d_in[8];
    const float* ssm_out_w = (const float*)d_in[9];
    const float* final_w   = (const float*)d_in[10];
    const float* final_b   = (const float*)d_in[11];
    float* out = (float*)d_out;

    float *xz, *xc, *xdbl, *delta, *y, *mid, *P, *He, *Hi;
    cudaGetSymbolAddress((void**)&xz, g_xz);
    cudaGetSymbolAddress((void**)&xc, g_xc);
    cudaGetSymbolAddress((void**)&xdbl, g_xdbl);
    cudaGetSymbolAddress((void**)&delta, g_delta);
    cudaGetSymbolAddress((void**)&y, g_y);
    cudaGetSymbolAddress((void**)&mid, g_mid);
    cudaGetSymbolAddress((void**)&P, g_P);
    cudaGetSymbolAddress((void**)&He, g_He);
    cudaGetSymbolAddress((void**)&Hi, g_Hi);

    // 1. in_proj: (4096,1024) x (4096,1024)^T -> xz (4096,4096)
    hmma_gemm<EPI_NONE><<<dim3(2 * DINNER / 128, BL / 128), 256>>>(
        x, DMODEL, in_proj_w, DMODEL, xz, 2 * DINNER, 2 * DINNER, DMODEL, nullptr);

    // 2. causal depthwise conv + SiLU -> xc (4096,2048)
    conv_silu_kernel<<<dim3(DINNER / 256, LL / 8, BB), 256>>>(xz, conv_w, conv_b, xc);

    // 3. x_proj: (4096,2048) x (96,2048)^T -> xdbl (4096,96)
    hmma_gemm<EPI_NONE><<<dim3(1, BL / 128), 256>>>(
        xc, DINNER, x_proj_w, DINNER, xdbl, 96, 96, DINNER, nullptr);

    // 4. dt_proj + softplus: (4096,64) x (2048,64)^T -> delta (4096,2048)
    hmma_gemm<EPI_SOFTPLUS><<<dim3(DINNER / 128, BL / 128), 256>>>(
        xdbl, 96, dt_proj_w, DTRANK, delta, DINNER, DINNER, DTRANK, dt_proj_b);

    // 5. chunked selective scan (fused D-skip + SiLU(z) gate) -> y
    scan_phaseA<<<dim3(DINNER / 256, NCHUNK, BB), 256>>>(delta, xc, xdbl, A_log, P, He);
    scan_phaseB<<<dim3((BB * DINNER * DSTATE) / 256), 256>>>(P, He, Hi);
    scan_phaseC<<<dim3(DINNER / 256, NCHUNK, BB), 256>>>(delta, xc, xdbl, A_log,
                                                         Dw, xz, Hi, y);

    // 6. out_proj: (4096,2048) x (1024,2048)^T -> mid (4096,1024)
    hmma_gemm<EPI_NONE><<<dim3(DMODEL / 128, BL / 128), 256>>>(
        y, DINNER, ssm_out_w, DINNER, mid, DMODEL, DMODEL, DINNER, nullptr);

    // 7. final linear + bias + SiLU -> d_out (4096,1024)
    hmma_gemm<EPI_SILU><<<dim3(DMODEL / 128, BL / 128), 256>>>(
        mid, DMODEL, final_w, DMODEL, out, DMODEL, DMODEL, DMODEL, final_b);
}

// round 8
// speedup vs baseline: 2.6232x; 1.1802x over previous
#include <cuda_runtime.h>
#include <cuda_bf16.h>
#include <cstdint>
#include <math.h>

// ---------------------------------------------------------------------------
// MambaSSMBlock on GB300 (harness PTX target = sm_103 plain => no tcgen05).
// GEMMs: warp-level HMMA mma.sync bf16, 3-pass hi/lo fp32-split, with
// cp.async double-buffered fp32 staging (R7) + split-K for x_proj (R7).
// ---------------------------------------------------------------------------

#define BB 2
#define LL 2048
#define DMODEL 1024
#define DINNER 2048
#define DSTATE 16
#define DTRANK 64
#define BL (BB * LL)
#define NCHUNK 16
#define CLEN (LL / NCHUNK)   // 128
#define XSPLIT 8             // split-K factor for x_proj

// ------------------------- scratch (device globals) ------------------------
__device__ float g_xz[(size_t)BL * 2 * DINNER];     // 4096 x 4096
__device__ float g_xc[(size_t)BL * DINNER];         // 4096 x 2048
__device__ float g_xdbl[(size_t)BL * 96];           // 4096 x 96
__device__ float g_xpart[(size_t)XSPLIT * BL * 96]; // split-K partials
__device__ float g_delta[(size_t)BL * DINNER];      // 4096 x 2048
__device__ float g_y[(size_t)BL * DINNER];          // 4096 x 2048
__device__ float g_mid[(size_t)BL * DMODEL];        // 4096 x 1024
__device__ float g_P[(size_t)BB * DINNER * NCHUNK * DSTATE];
__device__ float g_He[(size_t)BB * DINNER * NCHUNK * DSTATE];
__device__ float g_Hi[(size_t)BB * DINNER * NCHUNK * DSTATE];

// ------------------------------ helpers ------------------------------------
__device__ __forceinline__ float siluf(float x) {
    return x / (1.0f + __expf(-x));
}
__device__ __forceinline__ float softplusf(float x) {
    return (x > 20.0f) ? x : log1pf(__expf(x));
}

enum { EPI_NONE = 0, EPI_SOFTPLUS = 1, EPI_SILU = 2 };

// --------------------------- HMMA primitives --------------------------------
__device__ __forceinline__ void ldsm4(uint32_t* r, uint32_t addr) {
    asm volatile("ldmatrix.sync.aligned.m8n8.x4.shared.b16 {%0,%1,%2,%3}, [%4];"
                 : "=r"(r[0]), "=r"(r[1]), "=r"(r[2]), "=r"(r[3]) : "r"(addr));
}
__device__ __forceinline__ void ldsm2(uint32_t* r, uint32_t addr) {
    asm volatile("ldmatrix.sync.aligned.m8n8.x2.shared.b16 {%0,%1}, [%2];"
                 : "=r"(r[0]), "=r"(r[1]) : "r"(addr));
}
__device__ __forceinline__ void mma_bf16(float* c, const uint32_t* a, const uint32_t* b) {
    asm volatile(
        "mma.sync.aligned.m16n8k16.row.col.f32.bf16.bf16.f32 "
        "{%0,%1,%2,%3}, {%4,%5,%6,%7}, {%8,%9}, {%0,%1,%2,%3};"
        : "+f"(c[0]), "+f"(c[1]), "+f"(c[2]), "+f"(c[3])
        : "r"(a[0]), "r"(a[1]), "r"(a[2]), "r"(a[3]), "r"(b[0]), "r"(b[1]));
}
__device__ __forceinline__ void cp16(uint32_t dst, const void* src) {
    asm volatile("cp.async.cg.shared.global [%0], [%1], 16;" :: "r"(dst), "l"(src));
}
__device__ __forceinline__ void cp_commit() {
    asm volatile("cp.async.commit_group;" ::: "memory");
}
__device__ __forceinline__ void cp_wait0() {
    asm volatile("cp.async.wait_group 0;" ::: "memory");
}

// ---------------------------- HMMA split GEMM -------------------------------
// C[M,N] = A[M, koff:koff+Klen] * B[N, koff:koff+Klen]^T (+bias+activation)
// koff = blockIdx.z * Klen; C += blockIdx.z * part_stride (split-K partials).
// BM=BN=128, BK=32, 256 threads (8 warps 2x4, warp tile 64x32).
// cp.async double-buffered fp32 staging -> smem convert -> bf16 tiles.
#define SPAD 40   // bf16 row stride (32 data + 8 pad)
// dynamic smem layout (bytes):
//   [0, 32768)        fp32 staging stage 0 (A 16KB | B 16KB)
//   [32768, 65536)    fp32 staging stage 1
//   [65536, 75776)    sAhi   (128*40*2)
//   [75776, 86016)    sAlo
//   [86016, 96256)    sBhi
//   [96256, 106496)   sBlo
#define GSM_STAGE 32768
#define GSM_BF16 65536
#define GSM_TILE 10240
#define GSM_TOTAL 106496

template <int EPI>
__global__ void __launch_bounds__(256)
hmma_gemm(const float* __restrict__ A, int lda,
          const float* __restrict__ B, int ldb,
          float* __restrict__ C, int ldc,
          int N, int Klen, size_t part_stride,
          const float* __restrict__ bias)
{
    extern __shared__ char dyn[];
    const uint32_t sbase = (uint32_t)__cvta_generic_to_shared(dyn);

    const int tid = threadIdx.x;
    const int wid = tid >> 5;
    const int lane = tid & 31;
    const int m0 = blockIdx.y * 128;
    const int n0 = blockIdx.x * 128;
    const int koff = blockIdx.z * Klen;
    const int wm = (wid >> 2) * 64;
    const int wn = (wid & 3) * 32;

    C += (size_t)blockIdx.z * part_stride;

    const uint32_t baseAhi = sbase + GSM_BF16;
    const uint32_t baseAlo = baseAhi + GSM_TILE;
    const uint32_t baseBhi = baseAlo + GSM_TILE;
    const uint32_t baseBlo = baseBhi + GSM_TILE;
    __nv_bfloat16* sAhi = (__nv_bfloat16*)(dyn + GSM_BF16);
    __nv_bfloat16* sAlo = (__nv_bfloat16*)(dyn + GSM_BF16 + GSM_TILE);
    __nv_bfloat16* sBhi = (__nv_bfloat16*)(dyn + GSM_BF16 + 2 * GSM_TILE);
    __nv_bfloat16* sBlo = (__nv_bfloat16*)(dyn + GSM_BF16 + 3 * GSM_TILE);

    float acc[4][4][4];
#pragma unroll
    for (int i = 0; i < 4; i++)
#pragma unroll
        for (int j = 0; j < 4; j++)
#pragma unroll
            for (int k = 0; k < 4; k++) acc[i][j][k] = 0.0f;

    const int aoff = (lane & 15) * SPAD + (lane >> 4) * 8;           // ldsm x4
    const int boff = (lane & 7) * SPAD + ((lane >> 3) & 1) * 8;      // ldsm x2

    // per-thread load coordinates (4 16B chunks per tile)
    int lr[4], lc[4];
#pragma unroll
    for (int it = 0; it < 4; it++) {
        int i = tid + it * 256;
        lr[it] = i >> 3;
        lc[it] = (i & 7) * 4;
    }

    const int KT = Klen / 32;

    // prologue: stage 0
    {
        uint32_t dA = sbase;
        uint32_t dB = sbase + 16384;
#pragma unroll
        for (int it = 0; it < 4; it++)
            cp16(dA + (lr[it] * 32 + lc[it]) * 4,
                 A + (size_t)(m0 + lr[it]) * lda + koff + lc[it]);
#pragma unroll
        for (int it = 0; it < 4; it++) {
            int gn = n0 + lr[it]; if (gn > N - 1) gn = N - 1;
            cp16(dB + (lr[it] * 32 + lc[it]) * 4,
                 B + (size_t)gn * ldb + koff + lc[it]);
        }
        cp_commit();
    }

    for (int kt = 0; kt < KT; kt++) {
        cp_wait0();
        __syncthreads();   // staging data visible + previous MMA done with bf16 tiles

        if (kt + 1 < KT) {
            const int k1 = koff + (kt + 1) * 32;
            uint32_t dA = sbase + ((kt + 1) & 1) * GSM_STAGE;
            uint32_t dB = dA + 16384;
#pragma unroll
            for (int it = 0; it < 4; it++)
                cp16(dA + (lr[it] * 32 + lc[it]) * 4,
                     A + (size_t)(m0 + lr[it]) * lda + k1 + lc[it]);
#pragma unroll
            for (int it = 0; it < 4; it++) {
                int gn = n0 + lr[it]; if (gn > N - 1) gn = N - 1;
                cp16(dB + (lr[it] * 32 + lc[it]) * 4,
                     B + (size_t)gn * ldb + k1 + lc[it]);
            }
            cp_commit();
        }

        // convert fp32 staging (stage kt&1) -> bf16 hi/lo tiles
        {
            const float* fA = (const float*)(dyn + (kt & 1) * GSM_STAGE);
            const float* fB = fA + 4096;
#pragma unroll
            for (int it = 0; it < 4; it++) {
                int r = lr[it], c = lc[it];
                float4 v = *(const float4*)(fA + r * 32 + c);
                __nv_bfloat16 h0 = __float2bfloat16(v.x);
                __nv_bfloat16 h1 = __float2bfloat16(v.y);
                __nv_bfloat16 h2 = __float2bfloat16(v.z);
                __nv_bfloat16 h3 = __float2bfloat16(v.w);
                __nv_bfloat16 l0 = __float2bfloat16(v.x - __bfloat162float(h0));
                __nv_bfloat16 l1 = __float2bfloat16(v.y - __bfloat162float(h1));
                __nv_bfloat16 l2 = __float2bfloat16(v.z - __bfloat162float(h2));
                __nv_bfloat16 l3 = __float2bfloat16(v.w - __bfloat162float(h3));
                __nv_bfloat162* ph = (__nv_bfloat162*)&sAhi[r * SPAD + c];
                __nv_bfloat162* pl = (__nv_bfloat162*)&sAlo[r * SPAD + c];
                ph[0] = __nv_bfloat162(h0, h1); ph[1] = __nv_bfloat162(h2, h3);
                pl[0] = __nv_bfloat162(l0, l1); pl[1] = __nv_bfloat162(l2, l3);
            }
#pragma unroll
            for (int it = 0; it < 4; it++) {
                int r = lr[it], c = lc[it];
                float4 v = *(const float4*)(fB + r * 32 + c);
                __nv_bfloat16 h0 = __float2bfloat16(v.x);
                __nv_bfloat16 h1 = __float2bfloat16(v.y);
                __nv_bfloat16 h2 = __float2bfloat16(v.z);
                __nv_bfloat16 h3 = __float2bfloat16(v.w);
                __nv_bfloat16 l0 = __float2bfloat16(v.x - __bfloat162float(h0));
                __nv_bfloat16 l1 = __float2bfloat16(v.y - __bfloat162float(h1));
                __nv_bfloat16 l2 = __float2bfloat16(v.z - __bfloat162float(h2));
                __nv_bfloat16 l3 = __float2bfloat16(v.w - __bfloat162float(h3));
                __nv_bfloat162* ph = (__nv_bfloat162*)&sBhi[r * SPAD + c];
                __nv_bfloat162* pl = (__nv_bfloat162*)&sBlo[r * SPAD + c];
                ph[0] = __nv_bfloat162(h0, h1); ph[1] = __nv_bfloat162(h2, h3);
                pl[0] = __nv_bfloat162(l0, l1); pl[1] = __nv_bfloat162(l2, l3);
            }
        }
        __syncthreads();

        // ---- compute: 2 k16 halves x 3 passes ----
#pragma unroll
        for (int kh = 0; kh < 2; kh++) {
            uint32_t af[4][4], bf[4][2];
            const uint32_t ka = (uint32_t)(kh * 16) * 2;

            // pass 1: Ahi * Bhi
#pragma unroll
            for (int mi = 0; mi < 4; mi++)
                ldsm4(af[mi], baseAhi + ((wm + mi * 16) * SPAD + aoff) * 2 + ka);
#pragma unroll
            for (int ni = 0; ni < 4; ni++)
                ldsm2(bf[ni], baseBhi + ((wn + ni * 8) * SPAD + boff) * 2 + ka);
#pragma unroll
            for (int mi = 0; mi < 4; mi++)
#pragma unroll
                for (int ni = 0; ni < 4; ni++)
                    mma_bf16(acc[mi][ni], af[mi], bf[ni]);

            // pass 2: Ahi * Blo (reuse af)
#pragma unroll
            for (int ni = 0; ni < 4; ni++)
                ldsm2(bf[ni], baseBlo + ((wn + ni * 8) * SPAD + boff) * 2 + ka);
#pragma unroll
            for (int mi = 0; mi < 4; mi++)
#pragma unroll
                for (int ni = 0; ni < 4; ni++)
                    mma_bf16(acc[mi][ni], af[mi], bf[ni]);

            // pass 3: Alo * Bhi
#pragma unroll
            for (int mi = 0; mi < 4; mi++)
                ldsm4(af[mi], baseAlo + ((wm + mi * 16) * SPAD + aoff) * 2 + ka);
#pragma unroll
            for (int ni = 0; ni < 4; ni++)
                ldsm2(bf[ni], baseBhi + ((wn + ni * 8) * SPAD + boff) * 2 + ka);
#pragma unroll
            for (int mi = 0; mi < 4; mi++)
#pragma unroll
                for (int ni = 0; ni < 4; ni++)
                    mma_bf16(acc[mi][ni], af[mi], bf[ni]);
        }
    }

    __syncthreads();

    // ---- epilogue ----
    const int tg = lane >> 2;
    const int tc = (lane & 3) * 2;
#pragma unroll
    for (int mi = 0; mi < 4; mi++) {
#pragma unroll
        for (int ni = 0; ni < 4; ni++) {
#pragma unroll
            for (int h = 0; h < 2; h++) {
                int m = m0 + wm + mi * 16 + tg + h * 8;
#pragma unroll
                for (int s = 0; s < 2; s++) {
                    int n = n0 + wn + ni * 8 + tc + s;
                    if (n < N) {
                        float v = acc[mi][ni][h * 2 + s];
                        if (EPI == EPI_SOFTPLUS) v = softplusf(v + bias[n]);
                        else if (EPI == EPI_SILU) v = siluf(v + bias[n]);
                        C[(size_t)m * ldc + n] = v;
                    }
                }
            }
        }
    }
}

// ----------------------- split-K partial reduction --------------------------
__global__ void __launch_bounds__(256)
reduce_splitk(const float* __restrict__ part, float* __restrict__ out, int n)
{
    int i = blockIdx.x * 256 + threadIdx.x;
    if (i < n) {
        float s = 0.0f;
#pragma unroll
        for (int j = 0; j < XSPLIT; j++) s += part[(size_t)j * n + i];
        out[i] = s;
    }
}

// ------------------------ conv1d (causal depthwise) + SiLU ------------------
__global__ void __launch_bounds__(256)
conv_silu_kernel(const float* __restrict__ xz,
                 const float* __restrict__ conv_w,
                 const float* __restrict__ conv_b,
                 float* __restrict__ xc)
{
    const int d = blockIdx.x * 256 + threadIdx.x;     // 0..2047
    const int l0 = blockIdx.y * 8;                    // 0..2040
    const int b = blockIdx.z;

    const float w0 = conv_w[d * 4 + 0];
    const float w1 = conv_w[d * 4 + 1];
    const float w2 = conv_w[d * 4 + 2];
    const float w3 = conv_w[d * 4 + 3];
    const float cb = conv_b[d];

    float xv[11];
#pragma unroll
    for (int j = 0; j < 11; j++) {
        int l = l0 - 3 + j;
        xv[j] = (l >= 0) ? xz[((size_t)(b * LL + l)) * (2 * DINNER) + d] : 0.0f;
    }
#pragma unroll
    for (int i = 0; i < 8; i++) {
        float s = w0 * xv[i] + w1 * xv[i + 1] + w2 * xv[i + 2] + w3 * xv[i + 3] + cb;
        xc[((size_t)(b * LL + l0 + i)) * DINNER + d] = siluf(s);
    }
}

// ------------------------ selective scan: 3-phase chunked -------------------
__global__ void __launch_bounds__(256)
scan_phaseA(const float* __restrict__ delta,
            const float* __restrict__ xc,
            const float* __restrict__ xdbl,
            const float* __restrict__ A_log,
            float* __restrict__ Pout,
            float* __restrict__ Hend)
{
    const int d = blockIdx.x * 256 + threadIdx.x;
    const int c = blockIdx.y;
    const int b = blockIdx.z;

    float A2[DSTATE], h[DSTATE], P[DSTATE];
#pragma unroll
    for (int n = 0; n < DSTATE; n++) {
        A2[n] = -__expf(A_log[d * DSTATE + n]);
        h[n] = 0.0f;
        P[n] = 1.0f;
    }

    const size_t row0 = (size_t)(b * LL + c * CLEN);
    const float* drow = delta + row0 * DINNER + d;
    const float* urow = xc + row0 * DINNER + d;
    const float* bcrow = xdbl + row0 * 96 + 64;

    for (int t = 0; t < CLEN; t++) {
        float dlt = drow[(size_t)t * DINNER];
        float du = dlt * urow[(size_t)t * DINNER];
        const float4* bc = (const float4*)(bcrow + (size_t)t * 96);
        float Bv[DSTATE];
        float4 q;
        q = bc[0]; Bv[0] = q.x; Bv[1] = q.y; Bv[2] = q.z; Bv[3] = q.w;
        q = bc[1]; Bv[4] = q.x; Bv[5] = q.y; Bv[6] = q.z; Bv[7] = q.w;
        q = bc[2]; Bv[8] = q.x; Bv[9] = q.y; Bv[10] = q.z; Bv[11] = q.w;
        q = bc[3]; Bv[12] = q.x; Bv[13] = q.y; Bv[14] = q.z; Bv[15] = q.w;
#pragma unroll
        for (int n = 0; n < DSTATE; n++) {
            float a = __expf(dlt * A2[n]);
            P[n] *= a;
            h[n] = fmaf(a, h[n], du * Bv[n]);
        }
    }
    const size_t o = (((size_t)(b * DINNER + d)) * NCHUNK + c) * DSTATE;
#pragma unroll
    for (int n = 0; n < DSTATE; n++) {
        Pout[o + n] = P[n];
        Hend[o + n] = h[n];
    }
}

__global__ void __launch_bounds__(256)
scan_phaseB(const float* __restrict__ P,
            const float* __restrict__ He,
            float* __restrict__ Hi)
{
    const int idx = blockIdx.x * 256 + threadIdx.x;
    const int n = idx % DSTATE;
    const int bd = idx / DSTATE;
    float h = 0.0f;
    for (int c = 0; c < NCHUNK; c++) {
        const size_t o = (((size_t)bd) * NCHUNK + c) * DSTATE + n;
        Hi[o] = h;
        h = P[o] * h + He[o];
    }
}

__global__ void __launch_bounds__(256)
scan_phaseC(const float* __restrict__ delta,
            const float* __restrict__ xc,
            const float* __restrict__ xdbl,
            const float* __restrict__ A_log,
            const float* __restrict__ Dw,
            const float* __restrict__ xz,
            const float* __restrict__ Hi,
            float* __restrict__ y)
{
    const int d = blockIdx.x * 256 + threadIdx.x;
    const int c = blockIdx.y;
    const int b = blockIdx.z;

    float A2[DSTATE], h[DSTATE];
    const size_t ho = (((size_t)(b * DINNER + d)) * NCHUNK + c) * DSTATE;
#pragma unroll
    for (int n = 0; n < DSTATE; n++) {
        A2[n] = -__expf(A_log[d * DSTATE + n]);
        h[n] = Hi[ho + n];
    }
    const float Dd = Dw[d];

    const size_t row0 = (size_t)(b * LL + c * CLEN);
    const float* drow = delta + row0 * DINNER + d;
    const float* urow = xc + row0 * DINNER + d;
    const float* zrow = xz + row0 * (2 * DINNER) + DINNER + d;
    const float* bcrow = xdbl + row0 * 96 + 64;
    float* yrow = y + row0 * DINNER + d;

    for (int t = 0; t < CLEN; t++) {
        float dlt = drow[(size_t)t * DINNER];
        float u = urow[(size_t)t * DINNER];
        float du = dlt * u;
        const float4* bc = (const float4*)(bcrow + (size_t)t * 96);
        float Bv[DSTATE], Cv[DSTATE];
        float4 q;
        q = bc[0]; Bv[0] = q.x; Bv[1] = q.y; Bv[2] = q.z; Bv[3] = q.w;
        q = bc[1]; Bv[4] = q.x; Bv[5] = q.y; Bv[6] = q.z; Bv[7] = q.w;
        q = bc[2]; Bv[8] = q.x; Bv[9] = q.y; Bv[10] = q.z; Bv[11] = q.w;
        q = bc[3]; Bv[12] = q.x; Bv[13] = q.y; Bv[14] = q.z; Bv[15] = q.w;
        q = bc[4]; Cv[0] = q.x; Cv[1] = q.y; Cv[2] = q.z; Cv[3] = q.w;
        q = bc[5]; Cv[4] = q.x; Cv[5] = q.y; Cv[6] = q.z; Cv[7] = q.w;
        q = bc[6]; Cv[8] = q.x; Cv[9] = q.y; Cv[10] = q.z; Cv[11] = q.w;
        q = bc[7]; Cv[12] = q.x; Cv[13] = q.y; Cv[14] = q.z; Cv[15] = q.w;

        float acc = 0.0f;
#pragma unroll
        for (int n = 0; n < DSTATE; n++) {
            float a = __expf(dlt * A2[n]);
            h[n] = fmaf(a, h[n], du * Bv[n]);
            acc = fmaf(h[n], Cv[n], acc);
        }
        float z = zrow[(size_t)t * (2 * DINNER)];
        yrow[(size_t)t * DINNER] = (acc + u * Dd) * siluf(z);
    }
}

// ------------------------------- launcher -----------------------------------
extern "C" void kernel_launch(void* const* d_in, const int* in_sizes, int n_in,
                              void* d_out, int out_size)
{
    const float* x         = (const float*)d_in[0];
    const float* in_proj_w = (const float*)d_in[1];
    const float* conv_w    = (const float*)d_in[2];
    const float* conv_b    = (const float*)d_in[3];
    const float* x_proj_w  = (const float*)d_in[4];
    const float* dt_proj_w = (const float*)d_in[5];
    const float* dt_proj_b = (const float*)d_in[6];
    const float* A_log     = (const float*)d_in[7];
    const float* Dw        = (const float*)d_in[8];
    const float* ssm_out_w = (const float*)d_in[9];
    const float* final_w   = (const float*)d_in[10];
    const float* final_b   = (const float*)d_in[11];
    float* out = (float*)d_out;

    float *xz, *xc, *xdbl, *xpart, *delta, *y, *mid, *P, *He, *Hi;
    cudaGetSymbolAddress((void**)&xz, g_xz);
    cudaGetSymbolAddress((void**)&xc, g_xc);
    cudaGetSymbolAddress((void**)&xdbl, g_xdbl);
    cudaGetSymbolAddress((void**)&xpart, g_xpart);
    cudaGetSymbolAddress((void**)&delta, g_delta);
    cudaGetSymbolAddress((void**)&y, g_y);
    cudaGetSymbolAddress((void**)&mid, g_mid);
    cudaGetSymbolAddress((void**)&P, g_P);
    cudaGetSymbolAddress((void**)&He, g_He);
    cudaGetSymbolAddress((void**)&Hi, g_Hi);

    cudaFuncSetAttribute(hmma_gemm<EPI_NONE>,
                         cudaFuncAttributeMaxDynamicSharedMemorySize, GSM_TOTAL);
    cudaFuncSetAttribute(hmma_gemm<EPI_SOFTPLUS>,
                         cudaFuncAttributeMaxDynamicSharedMemorySize, GSM_TOTAL);
    cudaFuncSetAttribute(hmma_gemm<EPI_SILU>,
                         cudaFuncAttributeMaxDynamicSharedMemorySize, GSM_TOTAL);

    // 1. in_proj: (4096,1024) x (4096,1024)^T -> xz (4096,4096)
    hmma_gemm<EPI_NONE><<<dim3(2 * DINNER / 128, BL / 128), 256, GSM_TOTAL>>>(
        x, DMODEL, in_proj_w, DMODEL, xz, 2 * DINNER,
        2 * DINNER, DMODEL, 0, nullptr);

    // 2. causal depthwise conv + SiLU -> xc (4096,2048)
    conv_silu_kernel<<<dim3(DINNER / 256, LL / 8, BB), 256>>>(xz, conv_w, conv_b, xc);

    // 3. x_proj: (4096,2048) x (96,2048)^T -> xdbl (4096,96), split-K=8
    hmma_gemm<EPI_NONE><<<dim3(1, BL / 32 / 4, XSPLIT), 256, GSM_TOTAL>>>(
        xc, DINNER, x_proj_w, DINNER, xpart, 96,
        96, DINNER / XSPLIT, (size_t)BL * 96, nullptr);
    reduce_splitk<<<(BL * 96 + 255) / 256, 256>>>(xpart, xdbl, BL * 96);

    // 4. dt_proj + softplus: (4096,64) x (2048,64)^T -> delta (4096,2048)
    hmma_gemm<EPI_SOFTPLUS><<<dim3(DINNER / 128, BL / 128), 256, GSM_TOTAL>>>(
        xdbl, 96, dt_proj_w, DTRANK, delta, DINNER,
        DINNER, DTRANK, 0, dt_proj_b);

    // 5. chunked selective scan (fused D-skip + SiLU(z) gate) -> y
    scan_phaseA<<<dim3(DINNER / 256, NCHUNK, BB), 256>>>(delta, xc, xdbl, A_log, P, He);
    scan_phaseB<<<dim3((BB * DINNER * DSTATE) / 256), 256>>>(P, He, Hi);
    scan_phaseC<<<dim3(DINNER / 256, NCHUNK, BB), 256>>>(delta, xc, xdbl, A_log,
                                                         Dw, xz, Hi, y);

    // 6. out_proj: (4096,2048) x (1024,2048)^T -> mid (4096,1024)
    hmma_gemm<EPI_NONE><<<dim3(DMODEL / 128, BL / 128), 256, GSM_TOTAL>>>(
        y, DINNER, ssm_out_w, DINNER, mid, DMODEL,
        DMODEL, DINNER, 0, nullptr);

    // 7. final linear + bias + SiLU -> d_out (4096,1024)
    hmma_gemm<EPI_SILU><<<dim3(DMODEL / 128, BL / 128), 256, GSM_TOTAL>>>(
        mid, DMODEL, final_w, DMODEL, out, DMODEL,
        DMODEL, DMODEL, 0, final_b);
}